// round 2
// baseline (speedup 1.0000x reference)
#include <cuda_runtime.h>
#include <math.h>

#define IMGSZ 224
#define HW (IMGSZ*IMGSZ)     // 50176
#define NK 100
#define NP 16
#define NB 8
#define NT 196               // 14x14 tiles of 16x16 px

// ---------------- device scratch (static, no runtime alloc) ----------------
__device__ float g_A[NP*IMGSZ];                   // resize matrix [16,224]
__device__ float g_centers[NB][NK][5];            // SLIC centers
__device__ unsigned char g_labels[NB][HW];        // per-pixel labels
__device__ double g_part[NB][NT][NK][6];          // per-tile partial sums (7.5 MB)
__device__ float g_tmp[NB][NK][NP][IMGSZ][3];     // row-resized masked tiles (34.4 MB)

__device__ __forceinline__ float slic_ratio() {
    // COMPACT / S, S = sqrt(H*W/K); matches numpy double math then fp32 cast
    return (float)(10.0 / sqrt(224.0 * 224.0 / 100.0));
}

// ---------------- init: resize matrix + center init ----------------
__global__ void k_init(const float* __restrict__ x) {
    int b = blockIdx.x;
    int t = threadIdx.x;

    if (b == 0 && t < NP) {
        float sample = (t + 0.5f) * 14.0f - 0.5f;
        float total = 0.0f;
        for (int h = 0; h < IMGSZ; h++) {
            float d = fabsf(sample - (float)h) * (1.0f / 14.0f);
            float w = fmaxf(0.0f, 1.0f - d);
            g_A[t * IMGSZ + h] = w;
            total += w;
        }
        float inv = 1.0f / total;
        for (int h = 0; h < IMGSZ; h++) g_A[t * IMGSZ + h] *= inv;
    }

    if (t < NK) {
        const int cg[10] = {11, 33, 56, 78, 100, 123, 145, 168, 190, 212};
        int gy = t / 10, gx = t % 10;
        int h = cg[gy], w = cg[gx];
        const float* im = x + (size_t)b * 3 * HW;
        float ratio = slic_ratio();
        g_centers[b][t][0] = im[0 * HW + h * IMGSZ + w];
        g_centers[b][t][1] = im[1 * HW + h * IMGSZ + w];
        g_centers[b][t][2] = im[2 * HW + h * IMGSZ + w];
        g_centers[b][t][3] = (float)h * ratio;
        g_centers[b][t][4] = (float)w * ratio;
    }
}

// ---------------- fused assign + partial center sums, with safe pruning ------
// One block per 16x16 tile. Prologue builds the candidate-center list for this
// tile: center k is excluded iff rectMinSpatial2(k) > min_j rectMaxSpatial2(j) + 3
// (color distance^2 <= 3 since all colors lie in [0,1)). This is conservative,
// so labels are bit-identical to the full argmin. Candidates kept in ascending
// k order to preserve jnp.argmin's first-min tie-break.
__global__ __launch_bounds__(256) void k_assign_tile(const float* __restrict__ x,
                                                     int accumulate) {
    __shared__ float scen[NK][5];
    __shared__ float scen2[NK];
    __shared__ unsigned char scand[NK];
    __shared__ unsigned int bal[8];
    __shared__ int sminbits;
    __shared__ double acc[NK][6];

    int tile = blockIdx.x, b = blockIdx.y, t = threadIdx.x;
    int lane = t & 31, warp = t >> 5;
    const float ratio = slic_ratio();
    int tr = tile / 14, tc = tile - tr * 14;

    if (t == 0) sminbits = 0x7f7fffff;   // +FLT_MAX
    __syncthreads();

    // ---- candidate prologue ----
    float rmin = 1e30f, rmax = 1e30f;
    float c0 = 0.f, c1 = 0.f, c2 = 0.f, c3 = 0.f, c4 = 0.f;
    if (t < NK) {
        c0 = g_centers[b][t][0];
        c1 = g_centers[b][t][1];
        c2 = g_centers[b][t][2];
        c3 = g_centers[b][t][3];
        c4 = g_centers[b][t][4];
        float ylo = (float)(tr * 16) * ratio, yhi = (float)(tr * 16 + 15) * ratio;
        float xlo = (float)(tc * 16) * ratio, xhi = (float)(tc * 16 + 15) * ratio;
        float dy0 = fmaxf(0.0f, fmaxf(ylo - c3, c3 - yhi));
        float dx0 = fmaxf(0.0f, fmaxf(xlo - c4, c4 - xhi));
        float dy1 = fmaxf(c3 - ylo, yhi - c3);
        float dx1 = fmaxf(c4 - xlo, xhi - c4);
        rmin = dy0 * dy0 + dx0 * dx0;
        rmax = dy1 * dy1 + dx1 * dx1;
    }
    float v = rmax;
#pragma unroll
    for (int o = 16; o; o >>= 1) v = fminf(v, __shfl_xor_sync(0xffffffffu, v, o));
    if (lane == 0) atomicMin(&sminbits, __float_as_int(v));  // nonneg floats: int-order == float-order
    __syncthreads();
    float thresh = __int_as_float(sminbits) + 3.001f;        // +eps margin over color bound
    bool keep = (t < NK) && (rmin <= thresh);
    unsigned int m = __ballot_sync(0xffffffffu, keep);
    if (lane == 0) bal[warp] = m;
    __syncthreads();
    if (keep) {
        int slot = __popc(m & ((1u << lane) - 1u));
        for (int w = 0; w < warp; w++) slot += __popc(bal[w]);
        scand[slot] = (unsigned char)t;
        scen[slot][0] = c0; scen[slot][1] = c1; scen[slot][2] = c2;
        scen[slot][3] = c3; scen[slot][4] = c4;
        scen2[slot] = c0*c0 + c1*c1 + c2*c2 + c3*c3 + c4*c4;
    }
    double* accf = &acc[0][0];
    for (int j = t; j < NK * 6; j += 256) accf[j] = 0.0;
    __syncthreads();
    int nc = 0;
#pragma unroll
    for (int w = 0; w < 8; w++) nc += __popc(bal[w]);

    // ---- per-pixel assignment ----
    int py = tr * 16 + (t >> 4), px = tc * 16 + (t & 15);
    int i = py * IMGSZ + px;
    const float* im = x + (size_t)b * 3 * HW;
    float f0 = im[i];
    float f1 = im[HW + i];
    float f2 = im[2 * HW + i];
    float f3 = (float)py * ratio;
    float f4 = (float)px * ratio;
    float fsq = f0*f0 + f1*f1 + f2*f2 + f3*f3 + f4*f4;

    float best = 3.4e38f;
    int bs = 0;
    for (int s = 0; s < nc; s++) {
        float dot = f0 * scen[s][0];
        dot = fmaf(f1, scen[s][1], dot);
        dot = fmaf(f2, scen[s][2], dot);
        dot = fmaf(f3, scen[s][3], dot);
        dot = fmaf(f4, scen[s][4], dot);
        float d = fsq + scen2[s] - 2.0f * dot;
        if (d < best) { best = d; bs = s; }     // strict < + ascending k => first-min
    }
    int kk = scand[bs];
    g_labels[b][i] = (unsigned char)kk;

    if (accumulate) {
        atomicAdd(&acc[kk][0], (double)f0);
        atomicAdd(&acc[kk][1], (double)f1);
        atomicAdd(&acc[kk][2], (double)f2);
        atomicAdd(&acc[kk][3], (double)f3);
        atomicAdd(&acc[kk][4], (double)f4);
        atomicAdd(&acc[kk][5], 1.0);
        __syncthreads();
        double* gp = &g_part[b][tile][0][0];
        for (int j = t; j < NK * 6; j += 256) gp[j] = accf[j];
    }
}

// ---------------- reduce tile partials -> new centers ----------------
__global__ __launch_bounds__(224) void k_reduce() {
    int k = blockIdx.x, b = blockIdx.y, t = threadIdx.x;
    int lane = t & 31, warp = t >> 5;
    double s[6] = {0, 0, 0, 0, 0, 0};
    if (t < NT) {
        const double* p = &g_part[b][t][k][0];
#pragma unroll
        for (int j = 0; j < 6; j++) s[j] = p[j];
    }
#pragma unroll
    for (int o = 16; o; o >>= 1) {
#pragma unroll
        for (int j = 0; j < 6; j++) s[j] += __shfl_down_sync(0xffffffffu, s[j], o);
    }
    __shared__ double red[7][6];
    if (lane == 0) {
#pragma unroll
        for (int j = 0; j < 6; j++) red[warp][j] = s[j];
    }
    __syncthreads();
    if (t == 0) {
        double a[6] = {0, 0, 0, 0, 0, 0};
#pragma unroll
        for (int w = 0; w < 7; w++)
#pragma unroll
            for (int j = 0; j < 6; j++) a[j] += red[w][j];
        if (a[5] > 0.0) {
            double inv = 1.0 / a[5];
            g_centers[b][k][0] = (float)(a[0] * inv);
            g_centers[b][k][1] = (float)(a[1] * inv);
            g_centers[b][k][2] = (float)(a[2] * inv);
            g_centers[b][k][3] = (float)(a[3] * inv);
            g_centers[b][k][4] = (float)(a[4] * inv);
        }
    }
}

// ---------------- zero the tmp scratch ----------------
__global__ void k_zero_tmp() {
    size_t n4 = (size_t)NB * NK * NP * IMGSZ * 3 / 4;
    size_t i = (size_t)blockIdx.x * blockDim.x + threadIdx.x;
    if (i < n4) reinterpret_cast<float4*>(g_tmp)[i] = make_float4(0.f, 0.f, 0.f, 0.f);
}

// ---------------- stage 1: row-resize masked image (scatter by label) --------
__global__ __launch_bounds__(256) void k_stage1(const float* __restrict__ x) {
    int b = blockIdx.y;
    int i = blockIdx.x * blockDim.x + threadIdx.x;
    if (i >= HW) return;
    int h = i / IMGSZ, w = i - h * IMGSZ;
    int k = g_labels[b][i];
    const float* im = x + (size_t)b * 3 * HW;
    float r = im[i], g = im[HW + i], bl = im[2 * HW + i];

    int q0 = max(0, (int)ceilf((h - 20.5f) * (1.0f / 14.0f)));
    int q1 = min(NP - 1, (int)floorf((h + 7.5f) * (1.0f / 14.0f)));
    for (int q = q0; q <= q1; q++) {
        float wt = g_A[q * IMGSZ + h];
        if (wt != 0.0f) {
            float* dst = &g_tmp[b][k][q][w][0];
            atomicAdd(dst + 0, wt * r);
            atomicAdd(dst + 1, wt * g);
            atomicAdd(dst + 2, wt * bl);
        }
    }
}

// ---------------- stage 2: column-resize + output permutation ----------------
__global__ __launch_bounds__(64) void k_stage2(float* __restrict__ out) {
    int b = blockIdx.y;
    int kp = blockIdx.x;             // k*16 + p
    int k = kp >> 4, p = kp & 15;
    __shared__ float srow[IMGSZ * 3];
    int t = threadIdx.x;
    const float* tp = &g_tmp[b][k][p][0][0];
    for (int j = t; j < IMGSZ * 3; j += 64) srow[j] = tp[j];
    __syncthreads();
    if (t < 48) {
        int q = t / 3, c = t - q * 3;
        const float* Aq = &g_A[q * IMGSZ];
        float acc = 0.0f;
#pragma unroll 8
        for (int w = 0; w < IMGSZ; w++) acc = fmaf(Aq[w], srow[w * 3 + c], acc);
        int lin = ((k * 16 + p) * 16 + q) * 3 + c;
        int kc = lin >> 8;
        int s  = lin & 255;
        out[((size_t)b * 256 + s) * 300 + kc] = acc;
    }
}

// ---------------- launch ----------------
extern "C" void kernel_launch(void* const* d_in, const int* in_sizes, int n_in,
                              void* d_out, int out_size) {
    const float* x = (const float*)d_in[0];
    float* out = (float*)d_out;

    k_init<<<NB, 128>>>(x);

    dim3 gt(NT, NB);                    // 196 x 8
    dim3 gr(NK, NB);                    // 100 x 8
    for (int it = 0; it < 10; it++) {
        k_assign_tile<<<gt, 256>>>(x, 1);
        k_reduce<<<gr, 224>>>();
    }
    k_assign_tile<<<gt, 256>>>(x, 0);   // final labels only

    size_t n4 = (size_t)NB * NK * NP * IMGSZ * 3 / 4;
    k_zero_tmp<<<(unsigned)((n4 + 255) / 256), 256>>>();

    dim3 g1((HW + 255) / 256, NB);
    k_stage1<<<g1, 256>>>(x);

    dim3 g2(NK * NP, NB);
    k_stage2<<<g2, 64>>>(out);
}